// round 1
// baseline (speedup 1.0000x reference)
#include <cuda_runtime.h>
#include <cuda_bf16.h>
#include <cstdint>

// Problem constants (fixed by the dataset)
#define M_TOK   256
#define K_IN    4096
#define N_OUT   11008
#define GROUPSZ 128
#define NGROUPS (K_IN / GROUPSZ)      // 32
#define QK_ROWS (K_IN / 8)            // 512  (each int32 packs 8 k-values)
#define QZ_COLS (N_OUT / 8)           // 1376 (each int32 packs 8 outfeatures)

// Tiling
#define BM 64
#define BN 128
#define BK 32
#define TM 4
#define TN 8
#define NTHREADS 256
#define SA_STRIDE (BM + 1)            // 65: conflict-free transpose store

__global__ __launch_bounds__(NTHREADS)
void qlin_fp32_kernel(const float* __restrict__ x,
                      const int*   __restrict__ qweight,
                      const int*   __restrict__ qzeros,
                      const float* __restrict__ scales,
                      const float* __restrict__ bias,
                      float* __restrict__ out)
{
    __shared__ float sA[BK * SA_STRIDE];     // [BK][BM+1], sA[k][m]
    __shared__ float sB[BK * BN];            // [BK][BN],  sB[k][n]

    const int tid = threadIdx.x;
    const int n0  = blockIdx.x * BN;
    const int m0  = blockIdx.y * BM;

    const int tm = tid >> 4;   // 0..15 -> 4 rows each
    const int tn = tid & 15;   // 0..15 -> 8 cols each

    float acc[TM][TN];
#pragma unroll
    for (int i = 0; i < TM; i++)
#pragma unroll
        for (int j = 0; j < TN; j++) acc[i][j] = 0.0f;

    // A fill mapping: thread t loads x[m0 + t/32 + 8*i][k0 + t%32], i = 0..7
    const int a_k = tid & 31;        // k offset within tile (coalesced)
    const int a_m = tid >> 5;        // base m offset (0..7), step 8

    // B fill mapping: idx in [0, 512) over 4 qweight rows x 128 cols
    // thread handles idx = tid and tid + 256
    for (int k0 = 0; k0 < K_IN; k0 += BK) {
        // ---- load A tile (64 x 32), transpose into sA[k][m] ----
        const float* xp = x + (long)(m0 + a_m) * K_IN + k0 + a_k;
#pragma unroll
        for (int i = 0; i < 8; i++) {
            sA[a_k * SA_STRIDE + a_m + 8 * i] = xp[(long)8 * i * K_IN];
        }

        // ---- dequantize B tile (32 x 128) into sB ----
        const int g = k0 >> 7;                 // group index (GROUPSZ=128 >= BK)
        const int krow0 = k0 >> 3;             // first qweight row of this tile
#pragma unroll
        for (int it = 0; it < 2; it++) {
            const int idx = tid + it * NTHREADS;     // 0..511
            const int kr  = idx >> 7;                // 0..3
            const int c   = idx & 127;               // col in tile
            const int o   = n0 + c;

            const unsigned int wpack = (unsigned int)qweight[(long)(krow0 + kr) * N_OUT + o];
            const unsigned int zpack = (unsigned int)qzeros[(long)g * QZ_COLS + (o >> 3)];
            const int z = (int)((zpack >> ((o & 7) * 4)) & 0xF) + 1;
            const float s  = scales[(long)g * N_OUT + o];
            const float zs = (float)z * s;

            float* sb = sB + kr * 8 * BN + c;
#pragma unroll
            for (int j = 0; j < 8; j++) {
                const int wv = (int)((wpack >> (4 * j)) & 0xF);
                sb[j * BN] = (float)wv * s - zs;
            }
        }
        __syncthreads();

        // ---- compute ----
#pragma unroll
        for (int kk = 0; kk < BK; kk++) {
            float a[TM];
            float b[TN];
#pragma unroll
            for (int i = 0; i < TM; i++)
                a[i] = sA[kk * SA_STRIDE + tm * TM + i];

            const float4 b0 = *(const float4*)&sB[kk * BN + tn * TN];
            const float4 b1 = *(const float4*)&sB[kk * BN + tn * TN + 4];
            b[0] = b0.x; b[1] = b0.y; b[2] = b0.z; b[3] = b0.w;
            b[4] = b1.x; b[5] = b1.y; b[6] = b1.z; b[7] = b1.w;

#pragma unroll
            for (int i = 0; i < TM; i++)
#pragma unroll
                for (int j = 0; j < TN; j++)
                    acc[i][j] = fmaf(a[i], b[j], acc[i][j]);
        }
        __syncthreads();
    }

    // ---- epilogue: add bias, store ----
    const int nbase = n0 + tn * TN;
    float bv[TN];
#pragma unroll
    for (int j = 0; j < TN; j++) bv[j] = bias[nbase + j];

#pragma unroll
    for (int i = 0; i < TM; i++) {
        const int m = m0 + tm * TM + i;
        float4 o0, o1;
        o0.x = acc[i][0] + bv[0];
        o0.y = acc[i][1] + bv[1];
        o0.z = acc[i][2] + bv[2];
        o0.w = acc[i][3] + bv[3];
        o1.x = acc[i][4] + bv[4];
        o1.y = acc[i][5] + bv[5];
        o1.z = acc[i][6] + bv[6];
        o1.w = acc[i][7] + bv[7];
        *(float4*)(out + (long)m * N_OUT + nbase)     = o0;
        *(float4*)(out + (long)m * N_OUT + nbase + 4) = o1;
    }
}

extern "C" void kernel_launch(void* const* d_in, const int* in_sizes, int n_in,
                              void* d_out, int out_size)
{
    const float* x       = (const float*)d_in[0];   // [256, 4096]
    const int*   qweight = (const int*)  d_in[1];   // [512, 11008]
    const int*   qzeros  = (const int*)  d_in[2];   // [32, 1376]
    const float* scales  = (const float*)d_in[3];   // [32, 11008]
    const float* bias    = (const float*)d_in[4];   // [11008]
    float*       out     = (float*)d_out;           // [256, 11008]

    dim3 grid(N_OUT / BN, M_TOK / BM);   // (86, 4) = 344 CTAs
    dim3 block(NTHREADS);
    qlin_fp32_kernel<<<grid, block>>>(x, qweight, qzeros, scales, bias, out);
}

// round 4
// speedup vs baseline: 3.3844x; 3.3844x over previous
#include <cuda_runtime.h>
#include <cuda_fp16.h>
#include <cstdint>

// ---------------- problem constants ----------------
#define M_TOK   256
#define K_IN    4096
#define N_OUT   11008
#define QZ_COLS 1376

// ---------------- scratch (device globals: allowed) ----------------
__device__ __half g_P[45088768];      // [N_OUT][K_IN] fp16 exact (w - z), k-permuted per 8
__device__ __half g_xhi[1048576];     // [M][K] fp16 hi, same k-permutation
__device__ __half g_xlo[1048576];     // [M][K] fp16 lo

// ---------------- split x: fp32 -> fp16 hi/lo, permute k within 8 ----------------
// permutation: position pairs (2p,2p+1) hold original (f[p], f[p+4])
__global__ __launch_bounds__(256) void split_x(const float* __restrict__ x)
{
    int t = blockIdx.x * 256 + threadIdx.x;          // 0..131071, 8 floats each
    const float4* x4 = (const float4*)x;
    float4 v0 = x4[(size_t)t * 2];
    float4 v1 = x4[(size_t)t * 2 + 1];
    float f[8] = {v0.x, v0.y, v0.z, v0.w, v1.x, v1.y, v1.z, v1.w};
    uint4 hi, lo;
    uint32_t* hp = (uint32_t*)&hi;
    uint32_t* lp = (uint32_t*)&lo;
#pragma unroll
    for (int p = 0; p < 4; p++) {
        __half h0 = __float2half_rn(f[p]);
        __half h1 = __float2half_rn(f[p + 4]);
        __half l0 = __float2half_rn(f[p]     - __half2float(h0));
        __half l1 = __float2half_rn(f[p + 4] - __half2float(h1));
        __half2 hh = __halves2half2(h0, h1);
        __half2 ll = __halves2half2(l0, l1);
        hp[p] = *(uint32_t*)&hh;
        lp[p] = *(uint32_t*)&ll;
    }
    *(uint4*)(g_xhi + (size_t)t * 8) = hi;
    *(uint4*)(g_xlo + (size_t)t * 8) = lo;
}

// ---------------- dequant: qweight -> g_P [n][k] fp16 (w - z) ----------------
__global__ __launch_bounds__(256) void dequant_kernel(const int* __restrict__ qweight,
                                                      const int* __restrict__ qzeros)
{
    __shared__ unsigned sw[32 * 65];
    const int tid = threadIdx.x;
    const int n0  = blockIdx.x * 64;
    const int kr0 = blockIdx.y * 32;
#pragma unroll
    for (int j = 0; j < 8; j++) {
        int i = tid + j * 256;
        int kr = i >> 6, c = i & 63;
        sw[kr * 65 + c] = (unsigned)qweight[(size_t)(kr0 + kr) * N_OUT + n0 + c];
    }
    __syncthreads();

    const int c   = tid >> 2;
    const int sub = tid & 3;
    const int n   = n0 + c;
    const int kbase = kr0 * 8 + sub * 64;     // 64-k span, within one group of 128
    const int g   = kbase >> 7;

    unsigned zp = (unsigned)qzeros[(size_t)g * QZ_COLS + (n >> 3)];
    int z1 = (int)((zp >> ((n & 7) * 4)) & 0xF) + 1;
    unsigned zbu = 0x64006400u + (unsigned)((z1 << 16) | z1);
    __half2 zb = *(__half2*)&zbu;

    __half* dst = g_P + (size_t)n * K_IN + kbase;
#pragma unroll
    for (int r = 0; r < 8; r++) {
        unsigned p = sw[(sub * 8 + r) * 65 + c];
        uint4 o;
        uint32_t* op = (uint32_t*)&o;
#pragma unroll
        for (int q = 0; q < 4; q++) {
            unsigned t = (p >> (4 * q)) & 0x000F000Fu;   // nibbles (v_q, v_{q+4})
            unsigned h = t | 0x64006400u;                // halves 1024+v
            __half2 r2 = __hsub2(*(__half2*)&h, zb);     // (1024+v) - (1024+z) = w - z
            op[q] = *(uint32_t*)&r2;
        }
        *(uint4*)(dst + r * 8) = o;
    }
}

// ---------------- GEMM: mma.sync fp16, BM=128 BN=64 BK=32, 4-stage cp.async ----------------
#define STAGES 4
#define STG_B  25600
#define A_LO_OFF 10240
#define B_OFF    20480
#define ROWB     80      // bytes per smem row (32 halves + 8 pad)

__device__ __forceinline__ uint32_t s2u(const void* p) {
    uint32_t a;
    asm("{ .reg .u64 t; cvta.to.shared.u64 t, %1; cvt.u32.u64 %0, t; }" : "=r"(a) : "l"(p));
    return a;
}
__device__ __forceinline__ void cp16(uint32_t d, const void* s) {
    asm volatile("cp.async.cg.shared.global [%0], [%1], 16;" :: "r"(d), "l"(s));
}
__device__ __forceinline__ void ldsm4(uint32_t* r, uint32_t a) {
    asm volatile("ldmatrix.sync.aligned.m8n8.x4.shared.b16 {%0,%1,%2,%3}, [%4];"
                 : "=r"(r[0]), "=r"(r[1]), "=r"(r[2]), "=r"(r[3]) : "r"(a));
}
__device__ __forceinline__ void mma16816(float* c, const uint32_t* a, const uint32_t* b) {
    asm volatile("mma.sync.aligned.m16n8k16.row.col.f32.f16.f16.f32 "
                 "{%0,%1,%2,%3}, {%4,%5,%6,%7}, {%8,%9}, {%0,%1,%2,%3};"
                 : "+f"(c[0]), "+f"(c[1]), "+f"(c[2]), "+f"(c[3])
                 : "r"(a[0]), "r"(a[1]), "r"(a[2]), "r"(a[3]), "r"(b[0]), "r"(b[1]));
}

__global__ __launch_bounds__(256, 1)
void qlin_mma(const float* __restrict__ scales, const float* __restrict__ bias,
              float* __restrict__ out)
{
    extern __shared__ char smem[];
    const uint32_t sb = s2u(smem);
    float* sSc = (float*)(smem + STAGES * STG_B);   // [32 groups][64 cols]

    const int tid = threadIdx.x;
    const int l   = tid & 31;
    const int wid = tid >> 5;
    const int wm  = wid & 3;       // 4 warps along m (32 each)
    const int wn  = wid >> 2;      // 2 warps along n (32 each)
    const int n0  = blockIdx.x * 64;
    const int m0  = blockIdx.y * 128;

    // preload scales for this n-slice
#pragma unroll
    for (int j = 0; j < 8; j++) {
        int idx = tid + j * 256;
        sSc[idx] = scales[(size_t)(idx >> 6) * N_OUT + n0 + (idx & 63)];
    }

    // cp.async mapping
    const int arow = tid >> 1, ac = (tid & 1) * 16;   // halves
    const int brow = tid >> 2, bc = (tid & 3) * 8;    // halves
    const __half* gAh = g_xhi + (size_t)(m0 + arow) * K_IN + ac;
    const __half* gAl = g_xlo + (size_t)(m0 + arow) * K_IN + ac;
    const __half* gB  = g_P   + (size_t)(n0 + brow) * K_IN + bc;
    const uint32_t dAoff = (uint32_t)(arow * ROWB + ac * 2);
    const uint32_t dBoff = (uint32_t)(B_OFF + brow * ROWB + bc * 2);

    auto issue = [&](int st, int k0) {
        uint32_t base = sb + st * STG_B;
        if (k0 < K_IN) {
            uint32_t da = base + dAoff;
            cp16(da,      gAh + k0);
            cp16(da + 16, gAh + k0 + 8);
            cp16(da + A_LO_OFF,      gAl + k0);
            cp16(da + A_LO_OFF + 16, gAl + k0 + 8);
            cp16(base + dBoff, gB + k0);
        }
        asm volatile("cp.async.commit_group;");
    };

    float acc_t[2][4][4], acc_g[2][4][4];
#pragma unroll
    for (int mi = 0; mi < 2; mi++)
#pragma unroll
        for (int ni = 0; ni < 4; ni++)
#pragma unroll
            for (int q = 0; q < 4; q++) { acc_t[mi][ni][q] = 0.f; acc_g[mi][ni][q] = 0.f; }

    issue(0, 0); issue(1, 32); issue(2, 64);

    // ldmatrix lane address offsets (bytes, relative to stage base)
    const uint32_t aLane = (uint32_t)((wm * 32 + (l & 15)) * ROWB + (l >> 4) * 16);
    const uint32_t bLane = (uint32_t)(B_OFF + (wn * 32 + (l >> 4) * 8 + (l & 7)) * ROWB + ((l >> 3) & 1) * 16);

    for (int it = 0; it < 128; it++) {
        asm volatile("cp.async.wait_group 2;" ::: "memory");
        __syncthreads();
        issue((it + 3) & 3, (it + 3) * 32);

        const uint32_t base = sb + (it & 3) * STG_B;
#pragma unroll
        for (int kk = 0; kk < 2; kk++) {
            uint32_t Ahi[2][4], Alo[2][4], Bf[4][2];
#pragma unroll
            for (int mi = 0; mi < 2; mi++) {
                uint32_t aa = base + aLane + mi * 16 * ROWB + kk * 32;
                ldsm4(Ahi[mi], aa);
                ldsm4(Alo[mi], aa + A_LO_OFF);
            }
#pragma unroll
            for (int bi = 0; bi < 2; bi++) {
                uint32_t t[4];
                ldsm4(t, base + bLane + bi * 16 * ROWB + kk * 32);
                Bf[bi * 2][0] = t[0]; Bf[bi * 2][1] = t[1];
                Bf[bi * 2 + 1][0] = t[2]; Bf[bi * 2 + 1][1] = t[3];
            }
#pragma unroll
            for (int mi = 0; mi < 2; mi++)
#pragma unroll
                for (int ni = 0; ni < 4; ni++) {
                    mma16816(acc_g[mi][ni], Ahi[mi], Bf[ni]);
                    mma16816(acc_g[mi][ni], Alo[mi], Bf[ni]);
                }
        }

        if ((it & 3) == 3) {           // group boundary (GROUP=128 = 4 * BK32)
            int g = it >> 2;
#pragma unroll
            for (int ni = 0; ni < 4; ni++) {
                float2 s = *(float2*)&sSc[(g << 6) + wn * 32 + ni * 8 + ((l & 3) << 1)];
#pragma unroll
                for (int mi = 0; mi < 2; mi++) {
                    acc_t[mi][ni][0] += acc_g[mi][ni][0] * s.x;
                    acc_t[mi][ni][1] += acc_g[mi][ni][1] * s.y;
                    acc_t[mi][ni][2] += acc_g[mi][ni][2] * s.x;
                    acc_t[mi][ni][3] += acc_g[mi][ni][3] * s.y;
                    acc_g[mi][ni][0] = 0.f; acc_g[mi][ni][1] = 0.f;
                    acc_g[mi][ni][2] = 0.f; acc_g[mi][ni][3] = 0.f;
                }
            }
        }
    }

    // epilogue
#pragma unroll
    for (int ni = 0; ni < 4; ni++) {
        int col = n0 + wn * 32 + ni * 8 + ((l & 3) << 1);
        float b0 = bias[col], b1 = bias[col + 1];
#pragma unroll
        for (int mi = 0; mi < 2; mi++) {
            int row = m0 + wm * 32 + mi * 16 + (l >> 2);
            float2 v;
            v.x = acc_t[mi][ni][0] + b0;
            v.y = acc_t[mi][ni][1] + b1;
            *(float2*)&out[(size_t)row * N_OUT + col] = v;
            v.x = acc_t[mi][ni][2] + b0;
            v.y = acc_t[mi][ni][3] + b1;
            *(float2*)&out[(size_t)(row + 8) * N_OUT + col] = v;
        }
    }
}

// ---------------- launch ----------------
#define SMEM_DYN (STAGES * STG_B + 8192)   // 110592 bytes

extern "C" void kernel_launch(void* const* d_in, const int* in_sizes, int n_in,
                              void* d_out, int out_size)
{
    const float* x       = (const float*)d_in[0];   // [256, 4096]
    const int*   qweight = (const int*)  d_in[1];   // [512, 11008]
    const int*   qzeros  = (const int*)  d_in[2];   // [32, 1376]
    const float* scales  = (const float*)d_in[3];   // [32, 11008]
    const float* bias    = (const float*)d_in[4];   // [11008]
    float*       out     = (float*)d_out;           // [256, 11008]

    static bool s_init = false;
    if (!s_init) {
        cudaFuncSetAttribute(qlin_mma, cudaFuncAttributeMaxDynamicSharedMemorySize, SMEM_DYN);
        s_init = true;
    }

    split_x<<<512, 256>>>(x);
    dim3 dq_grid(N_OUT / 64, 512 / 32);             // (172, 16)
    dequant_kernel<<<dq_grid, 256>>>(qweight, qzeros);
    dim3 gm_grid(N_OUT / 64, M_TOK / 128);          // (172, 2)
    qlin_mma<<<gm_grid, 256, SMEM_DYN>>>(scales, bias, out);
}

// round 5
// speedup vs baseline: 3.6032x; 1.0647x over previous
#include <cuda_runtime.h>
#include <cuda_fp16.h>
#include <cstdint>

// ---------------- problem constants ----------------
#define M_TOK   256
#define K_IN    4096
#define N_OUT   11008
#define QZ_COLS 1376

// ---------------- scratch (device globals: allowed) ----------------
__device__ __half g_P[45088768];      // [N_OUT][K_IN] fp16 exact (w - z), k-permuted per 8
__device__ __half g_xhi[1048576];     // [M][K] fp16 hi, same k-permutation
__device__ __half g_xlo[1048576];     // [M][K] fp16 lo

// ---------------- split x: fp32 -> fp16 hi/lo, permute k within 8 ----------------
__global__ __launch_bounds__(256) void split_x(const float* __restrict__ x)
{
    int t = blockIdx.x * 256 + threadIdx.x;          // 0..131071, 8 floats each
    const float4* x4 = (const float4*)x;
    float4 v0 = x4[(size_t)t * 2];
    float4 v1 = x4[(size_t)t * 2 + 1];
    float f[8] = {v0.x, v0.y, v0.z, v0.w, v1.x, v1.y, v1.z, v1.w};
    uint4 hi, lo;
    uint32_t* hp = (uint32_t*)&hi;
    uint32_t* lp = (uint32_t*)&lo;
#pragma unroll
    for (int p = 0; p < 4; p++) {
        __half h0 = __float2half_rn(f[p]);
        __half h1 = __float2half_rn(f[p + 4]);
        __half l0 = __float2half_rn(f[p]     - __half2float(h0));
        __half l1 = __float2half_rn(f[p + 4] - __half2float(h1));
        __half2 hh = __halves2half2(h0, h1);
        __half2 ll = __halves2half2(l0, l1);
        hp[p] = *(uint32_t*)&hh;
        lp[p] = *(uint32_t*)&ll;
    }
    *(uint4*)(g_xhi + (size_t)t * 8) = hi;
    *(uint4*)(g_xlo + (size_t)t * 8) = lo;
}

// ---------------- dequant: qweight -> g_P [n][k] fp16 (w - z) ----------------
__global__ __launch_bounds__(256) void dequant_kernel(const int* __restrict__ qweight,
                                                      const int* __restrict__ qzeros)
{
    __shared__ unsigned sw[32 * 65];
    const int tid = threadIdx.x;
    const int n0  = blockIdx.x * 64;
    const int kr0 = blockIdx.y * 32;
#pragma unroll
    for (int j = 0; j < 8; j++) {
        int i = tid + j * 256;
        int kr = i >> 6, c = i & 63;
        sw[kr * 65 + c] = (unsigned)qweight[(size_t)(kr0 + kr) * N_OUT + n0 + c];
    }
    __syncthreads();

    const int c   = tid >> 2;
    const int sub = tid & 3;
    const int n   = n0 + c;
    const int kbase = kr0 * 8 + sub * 64;     // 64-k span, within one group of 128
    const int g   = kbase >> 7;

    unsigned zp = (unsigned)qzeros[(size_t)g * QZ_COLS + (n >> 3)];
    int z1 = (int)((zp >> ((n & 7) * 4)) & 0xF) + 1;
    unsigned zbu = 0x64006400u + (unsigned)((z1 << 16) | z1);
    __half2 zb = *(__half2*)&zbu;

    __half* dst = g_P + (size_t)n * K_IN + kbase;
#pragma unroll
    for (int r = 0; r < 8; r++) {
        unsigned p = sw[(sub * 8 + r) * 65 + c];
        uint4 o;
        uint32_t* op = (uint32_t*)&o;
#pragma unroll
        for (int q = 0; q < 4; q++) {
            unsigned t = (p >> (4 * q)) & 0x000F000Fu;   // nibbles (v_q, v_{q+4})
            unsigned h = t | 0x64006400u;                // halves 1024+v
            __half2 r2 = __hsub2(*(__half2*)&h, zb);     // (1024+v) - (1024+z) = w - z
            op[q] = *(uint32_t*)&r2;
        }
        *(uint4*)(dst + r * 8) = o;
    }
}

// ---------------- GEMM: mma.sync fp16, BM=128 BN=64 BK=32, 3-stage cp.async ----------------
#define STAGES 3
#define STG_B  25600
#define A_LO_OFF 10240
#define B_OFF    20480
#define ROWB     80      // bytes per smem row (32 halves + 8 pad)

__device__ __forceinline__ uint32_t s2u(const void* p) {
    uint32_t a;
    asm("{ .reg .u64 t; cvta.to.shared.u64 t, %1; cvt.u32.u64 %0, t; }" : "=r"(a) : "l"(p));
    return a;
}
__device__ __forceinline__ void cp16(uint32_t d, const void* s) {
    asm volatile("cp.async.cg.shared.global [%0], [%1], 16;" :: "r"(d), "l"(s));
}
__device__ __forceinline__ void ldsm4(uint32_t* r, uint32_t a) {
    asm volatile("ldmatrix.sync.aligned.m8n8.x4.shared.b16 {%0,%1,%2,%3}, [%4];"
                 : "=r"(r[0]), "=r"(r[1]), "=r"(r[2]), "=r"(r[3]) : "r"(a));
}
__device__ __forceinline__ void mma16816(float* c, const uint32_t* a, const uint32_t* b) {
    asm volatile("mma.sync.aligned.m16n8k16.row.col.f32.f16.f16.f32 "
                 "{%0,%1,%2,%3}, {%4,%5,%6,%7}, {%8,%9}, {%0,%1,%2,%3};"
                 : "+f"(c[0]), "+f"(c[1]), "+f"(c[2]), "+f"(c[3])
                 : "r"(a[0]), "r"(a[1]), "r"(a[2]), "r"(a[3]), "r"(b[0]), "r"(b[1]));
}

__global__ __launch_bounds__(256, 2)
void qlin_mma(const float* __restrict__ scales, const float* __restrict__ bias,
              float* __restrict__ out)
{
    extern __shared__ char smem[];
    const uint32_t sb = s2u(smem);
    float* sSc = (float*)(smem + STAGES * STG_B);   // [32 groups][64 cols]

    const int tid = threadIdx.x;
    const int l   = tid & 31;
    const int wid = tid >> 5;
    const int wm  = wid & 3;       // 4 warps along m (32 each)
    const int wn  = wid >> 2;      // 2 warps along n (32 each)
    const int m0  = blockIdx.x * 128;    // x = m block (2) -> adjacent CTAs share B slice
    const int n0  = blockIdx.y * 64;     // y = n block (172)

    // preload scales for this n-slice
#pragma unroll
    for (int j = 0; j < 8; j++) {
        int idx = tid + j * 256;
        sSc[idx] = scales[(size_t)(idx >> 6) * N_OUT + n0 + (idx & 63)];
    }

    // cp.async mapping
    const int arow = tid >> 1, ac = (tid & 1) * 16;   // halves
    const int brow = tid >> 2, bc = (tid & 3) * 8;    // halves
    const __half* gAh = g_xhi + (size_t)(m0 + arow) * K_IN + ac;
    const __half* gAl = g_xlo + (size_t)(m0 + arow) * K_IN + ac;
    const __half* gB  = g_P   + (size_t)(n0 + brow) * K_IN + bc;
    const uint32_t dAoff = (uint32_t)(arow * ROWB + ac * 2);
    const uint32_t dBoff = (uint32_t)(B_OFF + brow * ROWB + bc * 2);

    auto issue = [&](int st, int k0) {
        uint32_t base = sb + st * STG_B;
        if (k0 < K_IN) {
            uint32_t da = base + dAoff;
            cp16(da,      gAh + k0);
            cp16(da + 16, gAh + k0 + 8);
            cp16(da + A_LO_OFF,      gAl + k0);
            cp16(da + A_LO_OFF + 16, gAl + k0 + 8);
            cp16(base + dBoff, gB + k0);
        }
        asm volatile("cp.async.commit_group;");
    };

    float acc_t[2][4][4], acc_g[2][4][4];
#pragma unroll
    for (int mi = 0; mi < 2; mi++)
#pragma unroll
        for (int ni = 0; ni < 4; ni++)
#pragma unroll
            for (int q = 0; q < 4; q++) { acc_t[mi][ni][q] = 0.f; acc_g[mi][ni][q] = 0.f; }

    issue(0, 0); issue(1, 32);

    // ldmatrix lane address offsets (bytes, relative to stage base)
    const uint32_t aLane = (uint32_t)((wm * 32 + (l & 15)) * ROWB + (l >> 4) * 16);
    const uint32_t bLane = (uint32_t)(B_OFF + (wn * 32 + (l >> 4) * 8 + (l & 7)) * ROWB + ((l >> 3) & 1) * 16);

    int stage = 0;
    for (int it = 0; it < 128; it++) {
        asm volatile("cp.async.wait_group 1;" ::: "memory");
        __syncthreads();
        {
            int nst = stage + 2; if (nst >= STAGES) nst -= STAGES;
            issue(nst, (it + 2) * 32);
        }

        const uint32_t base = sb + stage * STG_B;
#pragma unroll
        for (int kk = 0; kk < 2; kk++) {
            uint32_t Ahi[2][4], Alo[2][4], Bf[4][2];
#pragma unroll
            for (int mi = 0; mi < 2; mi++) {
                uint32_t aa = base + aLane + mi * 16 * ROWB + kk * 32;
                ldsm4(Ahi[mi], aa);
                ldsm4(Alo[mi], aa + A_LO_OFF);
            }
#pragma unroll
            for (int bi = 0; bi < 2; bi++) {
                uint32_t t[4];
                ldsm4(t, base + bLane + bi * 16 * ROWB + kk * 32);
                Bf[bi * 2][0] = t[0]; Bf[bi * 2][1] = t[1];
                Bf[bi * 2 + 1][0] = t[2]; Bf[bi * 2 + 1][1] = t[3];
            }
#pragma unroll
            for (int mi = 0; mi < 2; mi++)
#pragma unroll
                for (int ni = 0; ni < 4; ni++) {
                    mma16816(acc_g[mi][ni], Ahi[mi], Bf[ni]);
                    mma16816(acc_g[mi][ni], Alo[mi], Bf[ni]);
                }
        }

        if ((it & 3) == 3) {           // group boundary (GROUP=128 = 4 * BK32)
            int g = it >> 2;
#pragma unroll
            for (int ni = 0; ni < 4; ni++) {
                float2 s = *(float2*)&sSc[(g << 6) + wn * 32 + ni * 8 + ((l & 3) << 1)];
#pragma unroll
                for (int mi = 0; mi < 2; mi++) {
                    acc_t[mi][ni][0] += acc_g[mi][ni][0] * s.x;
                    acc_t[mi][ni][1] += acc_g[mi][ni][1] * s.y;
                    acc_t[mi][ni][2] += acc_g[mi][ni][2] * s.x;
                    acc_t[mi][ni][3] += acc_g[mi][ni][3] * s.y;
                    acc_g[mi][ni][0] = 0.f; acc_g[mi][ni][1] = 0.f;
                    acc_g[mi][ni][2] = 0.f; acc_g[mi][ni][3] = 0.f;
                }
            }
        }
        if (++stage >= STAGES) stage = 0;
    }

    // epilogue
#pragma unroll
    for (int ni = 0; ni < 4; ni++) {
        int col = n0 + wn * 32 + ni * 8 + ((l & 3) << 1);
        float b0 = bias[col], b1 = bias[col + 1];
#pragma unroll
        for (int mi = 0; mi < 2; mi++) {
            int row = m0 + wm * 32 + mi * 16 + (l >> 2);
            float2 v;
            v.x = acc_t[mi][ni][0] + b0;
            v.y = acc_t[mi][ni][1] + b1;
            *(float2*)&out[(size_t)row * N_OUT + col] = v;
            v.x = acc_t[mi][ni][2] + b0;
            v.y = acc_t[mi][ni][3] + b1;
            *(float2*)&out[(size_t)(row + 8) * N_OUT + col] = v;
        }
    }
}

// ---------------- launch ----------------
#define SMEM_DYN (STAGES * STG_B + 8192)   // 84992 bytes -> 2 CTAs/SM

extern "C" void kernel_launch(void* const* d_in, const int* in_sizes, int n_in,
                              void* d_out, int out_size)
{
    const float* x       = (const float*)d_in[0];   // [256, 4096]
    const int*   qweight = (const int*)  d_in[1];   // [512, 11008]
    const int*   qzeros  = (const int*)  d_in[2];   // [32, 1376]
    const float* scales  = (const float*)d_in[3];   // [32, 11008]
    const float* bias    = (const float*)d_in[4];   // [11008]
    float*       out     = (float*)d_out;           // [256, 11008]

    static bool s_init = false;
    if (!s_init) {
        cudaFuncSetAttribute(qlin_mma, cudaFuncAttributeMaxDynamicSharedMemorySize, SMEM_DYN);
        s_init = true;
    }

    split_x<<<512, 256>>>(x);
    dim3 dq_grid(N_OUT / 64, 512 / 32);             // (172, 16)
    dequant_kernel<<<dq_grid, 256>>>(qweight, qzeros);
    dim3 gm_grid(M_TOK / 128, N_OUT / 64);          // (2, 172): m fastest
    qlin_mma<<<gm_grid, 256, SMEM_DYN>>>(scales, bias, out);
}